// round 17
// baseline (speedup 1.0000x reference)
#include <cuda_runtime.h>
#include <cuda_fp16.h>
#include <cstdint>

#define NN 100000
#define DIM 64
#define NE 1250000
#define NBLK 98                    // ceil(100000 / 1024) scan blocks

// static device scratch — no allocation
__device__ __half g_h2h[NN * DIM];   // h2 = x @ W2, fp16
__device__ int g_deg[NN];
__device__ int g_start[NN + 1];
__device__ int g_cursor[NN];
__device__ int g_esrc[NE];
__device__ int g_bsum[NBLK];
__device__ int g_bflag[NBLK];

// ---------------------------------------------------------------------------
// Kernel 1: dual GEMM, 8x8 register tile (unchanged R15 winner).
// ---------------------------------------------------------------------------
#define S_XT 132
#define SMEM_BYTES ((64 * S_XT + 64 * 128) * 4)   // 66560

__global__ __launch_bounds__(256, 2) void gemm_dual(
    const float* __restrict__ x,
    const float* __restrict__ W1,
    const float* __restrict__ W2,
    float* __restrict__ h1,
    __half* __restrict__ h2h)
{
    extern __shared__ float dsm[];
    float* sxT = dsm;                 // [64][132]  sxT[k][r]
    float* sW  = dsm + 64 * S_XT;     // [64][128]  cols 0-63 W1, 64-127 W2

    const int tid  = threadIdx.x;
    const int lane = tid & 31;
    const int w    = tid >> 5;
    const int rowBase = blockIdx.x * 128;

    #pragma unroll
    for (int i = tid; i < 2048; i += 256) {
        const int m = i >> 10;
        const int j = i & 1023;
        const int k = j >> 4;
        const int c = (j & 15) * 4;
        const float4 v = ((const float4*)(m ? W2 : W1))[j];
        *(float4*)(sW + k * 128 + m * 64 + c) = v;
    }

    #pragma unroll
    for (int iter = 0; iter < 8; ++iter) {
        const int task = iter * 8 + w;
        const int r0 = (task & 31) * 4;
        const int k  = (task >> 5) * 32 + lane;
        const int gr = rowBase + r0;
        float v0 = 0.f, v1 = 0.f, v2 = 0.f, v3 = 0.f;
        if (gr + 0 < NN) v0 = x[(size_t)(gr + 0) * DIM + k];
        if (gr + 1 < NN) v1 = x[(size_t)(gr + 1) * DIM + k];
        if (gr + 2 < NN) v2 = x[(size_t)(gr + 2) * DIM + k];
        if (gr + 3 < NN) v3 = x[(size_t)(gr + 3) * DIM + k];
        *(float4*)(sxT + k * S_XT + r0) = make_float4(v0, v1, v2, v3);
    }
    __syncthreads();

    const int tc = tid & 15;
    const int tr = tid >> 4;
    const float* pa = sxT + 4 * tr;
    const float* pb = sW + 4 * tc;

    unsigned long long acc[8][4];
    #pragma unroll
    for (int r = 0; r < 8; ++r)
        #pragma unroll
        for (int p = 0; p < 4; ++p) acc[r][p] = 0ULL;

    #pragma unroll 4
    for (int k = 0; k < 64; ++k) {
        const ulonglong2 A0 = *(const ulonglong2*)(pa + k * S_XT);
        const ulonglong2 A1 = *(const ulonglong2*)(pa + k * S_XT + 64);
        const ulonglong2 B0 = *(const ulonglong2*)(pb + k * 128);
        const ulonglong2 B1 = *(const ulonglong2*)(pb + k * 128 + 64);

        unsigned long long a2[8];
        {
            float lo, hi;
            asm("mov.b64 {%0,%1}, %2;" : "=f"(lo), "=f"(hi) : "l"(A0.x));
            asm("mov.b64 %0, {%1,%1};" : "=l"(a2[0]) : "f"(lo));
            asm("mov.b64 %0, {%1,%1};" : "=l"(a2[1]) : "f"(hi));
            asm("mov.b64 {%0,%1}, %2;" : "=f"(lo), "=f"(hi) : "l"(A0.y));
            asm("mov.b64 %0, {%1,%1};" : "=l"(a2[2]) : "f"(lo));
            asm("mov.b64 %0, {%1,%1};" : "=l"(a2[3]) : "f"(hi));
            asm("mov.b64 {%0,%1}, %2;" : "=f"(lo), "=f"(hi) : "l"(A1.x));
            asm("mov.b64 %0, {%1,%1};" : "=l"(a2[4]) : "f"(lo));
            asm("mov.b64 %0, {%1,%1};" : "=l"(a2[5]) : "f"(hi));
            asm("mov.b64 {%0,%1}, %2;" : "=f"(lo), "=f"(hi) : "l"(A1.y));
            asm("mov.b64 %0, {%1,%1};" : "=l"(a2[6]) : "f"(lo));
            asm("mov.b64 %0, {%1,%1};" : "=l"(a2[7]) : "f"(hi));
        }
        #pragma unroll
        for (int r = 0; r < 8; ++r) {
            asm("fma.rn.f32x2 %0, %1, %2, %0;" : "+l"(acc[r][0]) : "l"(a2[r]), "l"(B0.x));
            asm("fma.rn.f32x2 %0, %1, %2, %0;" : "+l"(acc[r][1]) : "l"(a2[r]), "l"(B0.y));
            asm("fma.rn.f32x2 %0, %1, %2, %0;" : "+l"(acc[r][2]) : "l"(a2[r]), "l"(B1.x));
            asm("fma.rn.f32x2 %0, %1, %2, %0;" : "+l"(acc[r][3]) : "l"(a2[r]), "l"(B1.y));
        }
    }

    #pragma unroll
    for (int r = 0; r < 8; ++r) {
        const int gr = rowBase + ((r < 4) ? (4 * tr + r) : (64 + 4 * tr + r - 4));
        if (gr < NN) {
            ulonglong2 o1;
            o1.x = acc[r][0];
            o1.y = acc[r][1];
            *(ulonglong2*)(h1 + (size_t)gr * DIM + 4 * tc) = o1;

            float l0, h0, l1, hh1;
            uint32_t p0, p1;
            asm("mov.b64 {%0,%1}, %2;" : "=f"(l0), "=f"(h0) : "l"(acc[r][2]));
            asm("mov.b64 {%0,%1}, %2;" : "=f"(l1), "=f"(hh1) : "l"(acc[r][3]));
            asm("cvt.rn.f16x2.f32 %0, %1, %2;" : "=r"(p0) : "f"(h0), "f"(l0));
            asm("cvt.rn.f16x2.f32 %0, %1, %2;" : "=r"(p1) : "f"(hh1), "f"(l1));
            *(uint2*)(h2h + (size_t)gr * DIM + 4 * tc) = make_uint2(p0, p1);
        }
    }
}

// ---------------------------------------------------------------------------
// CSR-by-dst construction
// ---------------------------------------------------------------------------
__global__ __launch_bounds__(256) void zero_deg(
    int* __restrict__ deg, int* __restrict__ bflag)
{
    const int i = blockIdx.x * 256 + threadIdx.x;
    if (i < NN) deg[i] = 0;
    if (i < NBLK) bflag[i] = 0;
}

__global__ __launch_bounds__(256) void hist_dst(
    const int* __restrict__ dst, int* __restrict__ deg)
{
    const int e = blockIdx.x * 256 + threadIdx.x;
    if (e < NE) atomicAdd(&deg[__ldg(&dst[e])], 1);
}

// Fused exclusive scan with decoupled lookback (98 blocks, all co-resident).
__global__ __launch_bounds__(256) void scan_fused(
    const int* __restrict__ deg, int* __restrict__ start,
    int* __restrict__ cursor,
    volatile int* __restrict__ bsum, volatile int* __restrict__ bflag)
{
    __shared__ int s[256];
    __shared__ int s_off;
    const int tid  = threadIdx.x;
    const int bid  = blockIdx.x;
    const int base = bid * 1024 + tid * 4;

    int d0 = (base + 0 < NN) ? deg[base + 0] : 0;
    int d1 = (base + 1 < NN) ? deg[base + 1] : 0;
    int d2 = (base + 2 < NN) ? deg[base + 2] : 0;
    int d3 = (base + 3 < NN) ? deg[base + 3] : 0;
    const int mysum = d0 + d1 + d2 + d3;
    s[tid] = mysum;
    __syncthreads();

    for (int off = 1; off < 256; off <<= 1) {
        int v = (tid >= off) ? s[tid - off] : 0;
        __syncthreads();
        s[tid] += v;
        __syncthreads();
    }

    // publish this block's total
    if (tid == 255) {
        bsum[bid] = s[255];
        __threadfence();
        bflag[bid] = 1;
    }
    // lookback: thread 0 accumulates predecessor totals
    if (tid == 0) {
        int off = 0;
        for (int i = 0; i < bid; ++i) {
            while (bflag[i] == 0) { }
            off += bsum[i];
        }
        s_off = off;
    }
    __syncthreads();

    const int excl = s[tid] - mysum + s_off;
    if (base + 0 < NN) { start[base + 0] = excl;                 cursor[base + 0] = excl; }
    if (base + 1 < NN) { start[base + 1] = excl + d0;            cursor[base + 1] = excl + d0; }
    if (base + 2 < NN) { start[base + 2] = excl + d0 + d1;       cursor[base + 2] = excl + d0 + d1; }
    if (base + 3 < NN) { start[base + 3] = excl + d0 + d1 + d2;  cursor[base + 3] = excl + d0 + d1 + d2; }
    if (bid == 0 && tid == 0) start[NN] = NE;
}

__global__ __launch_bounds__(256) void reorder_edges(
    const int* __restrict__ src, const int* __restrict__ dst,
    int* __restrict__ cursor, int* __restrict__ esrc)
{
    const int e = blockIdx.x * 256 + threadIdx.x;
    if (e < NE) {
        const int d   = __ldg(&dst[e]);
        const int pos = atomicAdd(&cursor[d], 1);
        esrc[pos] = __ldg(&src[e]);
    }
}

// ---------------------------------------------------------------------------
// Fused gather-reduce + add h1 + ReLU. 16 threads per dst row; lane c owns
// 4 floats. Unroll-4 pipelining: 4 independent esrc+h2h loads in flight.
// ---------------------------------------------------------------------------
__global__ __launch_bounds__(256) void gather_relu(
    const int* __restrict__ start, const int* __restrict__ esrc,
    const __half* __restrict__ h2h, float* __restrict__ out)
{
    const int g = blockIdx.x * 16 + (threadIdx.x >> 4);   // dst row
    const int c = threadIdx.x & 15;
    if (g >= NN) return;

    const int s0 = __ldg(&start[g]);
    const int s1 = __ldg(&start[g + 1]);

    float a0 = 0.f, a1 = 0.f, a2 = 0.f, a3 = 0.f;
    const uint2* h2v = (const uint2*)h2h;

    int i = s0;
    for (; i + 4 <= s1; i += 4) {
        const int sa = __ldg(&esrc[i + 0]);
        const int sb = __ldg(&esrc[i + 1]);
        const int sc = __ldg(&esrc[i + 2]);
        const int sd = __ldg(&esrc[i + 3]);
        const uint2 ha = __ldg(h2v + (size_t)sa * 16 + c);
        const uint2 hb = __ldg(h2v + (size_t)sb * 16 + c);
        const uint2 hc = __ldg(h2v + (size_t)sc * 16 + c);
        const uint2 hd = __ldg(h2v + (size_t)sd * 16 + c);

        float2 f;
        f = __half22float2(*(const __half2*)&ha.x); a0 += f.x; a1 += f.y;
        f = __half22float2(*(const __half2*)&ha.y); a2 += f.x; a3 += f.y;
        f = __half22float2(*(const __half2*)&hb.x); a0 += f.x; a1 += f.y;
        f = __half22float2(*(const __half2*)&hb.y); a2 += f.x; a3 += f.y;
        f = __half22float2(*(const __half2*)&hc.x); a0 += f.x; a1 += f.y;
        f = __half22float2(*(const __half2*)&hc.y); a2 += f.x; a3 += f.y;
        f = __half22float2(*(const __half2*)&hd.x); a0 += f.x; a1 += f.y;
        f = __half22float2(*(const __half2*)&hd.y); a2 += f.x; a3 += f.y;
    }
    for (; i < s1; ++i) {
        const int s = __ldg(&esrc[i]);
        const uint2 hv = __ldg(h2v + (size_t)s * 16 + c);
        float2 f;
        f = __half22float2(*(const __half2*)&hv.x); a0 += f.x; a1 += f.y;
        f = __half22float2(*(const __half2*)&hv.y); a2 += f.x; a3 += f.y;
    }

    float4* p = (float4*)out + (size_t)g * 16 + c;
    float4 v = *p;
    v.x = fmaxf(v.x + a0, 0.f);
    v.y = fmaxf(v.y + a1, 0.f);
    v.z = fmaxf(v.z + a2, 0.f);
    v.w = fmaxf(v.w + a3, 0.f);
    *p = v;
}

// ---------------------------------------------------------------------------
// Inputs (metadata order): x [N,64] f32, edge_index [2,E] i32, W1 [64,64] f32,
// W2 [64,64] f32. Output: [N,64] f32.
// ---------------------------------------------------------------------------
extern "C" void kernel_launch(void* const* d_in, const int* in_sizes, int n_in,
                              void* d_out, int out_size)
{
    const float* x   = (const float*)d_in[0];
    const int*   ei  = (const int*)d_in[1];
    const float* W1  = (const float*)d_in[2];
    const float* W2  = (const float*)d_in[3];
    float*       out = (float*)d_out;

    const int* src = ei;        // edge_index[0]
    const int* dst = ei + NE;   // edge_index[1]

    __half* h2h;  cudaGetSymbolAddress((void**)&h2h,    g_h2h);
    int* deg;     cudaGetSymbolAddress((void**)&deg,    g_deg);
    int* startp;  cudaGetSymbolAddress((void**)&startp, g_start);
    int* cursor;  cudaGetSymbolAddress((void**)&cursor, g_cursor);
    int* esrc;    cudaGetSymbolAddress((void**)&esrc,   g_esrc);
    int* bsum;    cudaGetSymbolAddress((void**)&bsum,   g_bsum);
    int* bflag;   cudaGetSymbolAddress((void**)&bflag,  g_bflag);

    cudaFuncSetAttribute(gemm_dual, cudaFuncAttributeMaxDynamicSharedMemorySize,
                         SMEM_BYTES);

    // 1) out = x@W1, g_h2h = fp16(x@W2)
    gemm_dual<<<(NN + 127) / 128, 256, SMEM_BYTES>>>(x, W1, W2, out, h2h);

    // 2) CSR-by-dst: deg -> start (fused lookback scan) -> esrc (reorder)
    zero_deg<<<(NN + 255) / 256, 256>>>(deg, bflag);
    hist_dst<<<(NE + 255) / 256, 256>>>(dst, deg);
    scan_fused<<<NBLK, 256>>>(deg, startp, cursor, bsum, bflag);
    reorder_edges<<<(NE + 255) / 256, 256>>>(src, dst, cursor, esrc);

    // 3) out = relu(out + segment_sum(h2h[esrc]))
    gather_relu<<<(NN + 15) / 16, 256>>>(startp, esrc, h2h, out);
}